// round 14
// baseline (speedup 1.0000x reference)
#include <cuda_runtime.h>
#include <cuda_bf16.h>
#include <cstdint>

// ---------------------------------------------------------------------------
// Problem constants
//   x: [1024, 512, 128] fp32 -> logits [1024, 100] fp32
// ---------------------------------------------------------------------------
#define B_SZ    1024
#define T_STEPS 512
#define I_DIM   128
#define H_DIM   64
#define G_DIM   256                   // 4*H gate columns
#define E_DIM   128
#define C_DIM   100
#define M_ROWS  (B_SZ * T_STEPS)      // 524288

// ---------------------------------------------------------------------------
// Scratch (allocations forbidden -> __device__ globals)
// ---------------------------------------------------------------------------
__device__ float g_xg[(size_t)M_ROWS * G_DIM];    // 512 MB, layer-0 pre-gates
__device__ float g_out1[(size_t)M_ROWS * H_DIM];  // 128 MB, layer-0 hidden sequence
__device__ float g_hlast[B_SZ * H_DIM];           // layer-1 final hidden
__device__ float g_bfrag0[32 * 16 * 128];         // tf32 B-frags for gemm0 (layout verified)
__device__ float g_bias0[G_DIM];                  // b_ih0 + b_hh0
__device__ float g_bias1[G_DIM];                  // b_ih1 + b_hh1

// ---------------------------------------------------------------------------
// Small PTX helpers
// ---------------------------------------------------------------------------
__device__ __forceinline__ uint32_t f2tf32(float x) {
    uint32_t u;
    asm("cvt.rna.tf32.f32 %0, %1;" : "=r"(u) : "f"(x));
    return u;
}

__device__ __forceinline__ void mma_tf32(float* d, const uint32_t* a,
                                         uint32_t b0, uint32_t b1) {
    asm volatile(
        "mma.sync.aligned.m16n8k8.row.col.f32.tf32.tf32.f32 "
        "{%0,%1,%2,%3}, {%4,%5,%6,%7}, {%8,%9}, {%0,%1,%2,%3};"
        : "+f"(d[0]), "+f"(d[1]), "+f"(d[2]), "+f"(d[3])
        : "r"(a[0]), "r"(a[1]), "r"(a[2]), "r"(a[3]), "r"(b0), "r"(b1));
}

__device__ __forceinline__ float frcp(float x) {      // MUFU.RCP
    float r;
    asm("rcp.approx.f32 %0, %1;" : "=f"(r) : "f"(x));
    return r;
}
__device__ __forceinline__ float fast_sigmoid(float x) {
    return frcp(1.0f + __expf(-x));                   // ex2 + rcp, inf-safe
}
__device__ __forceinline__ float fast_tanh(float x) {
    return 2.0f * frcp(1.0f + __expf(-2.0f * x)) - 1.0f;
}

// ---------------------------------------------------------------------------
// Prep: fold biases; build tf32 B-fragment buffer for gemm0.
// B fragment (m16n8k8.row.col): b0 = W[n][k], b1 = W[n][k+4],
//   n = g*8 + lane/4, k = kit*8 + lane%4.   (layout verified R8/R9)
// ---------------------------------------------------------------------------
__global__ void prep_kernel(const float* __restrict__ Wih0,
                            const float* __restrict__ bih0,
                            const float* __restrict__ bhh0,
                            const float* __restrict__ bih1,
                            const float* __restrict__ bhh1) {
    int tid = blockIdx.x * blockDim.x + threadIdx.x;
    if (tid < G_DIM) {
        g_bias0[tid] = bih0[tid] + bhh0[tid];
        g_bias1[tid] = bih1[tid] + bhh1[tid];
    }
    if (tid < 32 * 16 * 32) {         // K=128 -> 16 k-iters, 32 gate groups
        int lane = tid & 31, kit = (tid >> 5) & 15, g = tid >> 9;
        int n = g * 8 + (lane >> 2);
        int k = kit * 8 + (lane & 3);
        uint32_t* base = (uint32_t*)(g_bfrag0 + (g * 16 + kit) * 128);
        base[lane * 2]     = f2tf32(Wih0[n * I_DIM + k]);
        base[lane * 2 + 1] = f2tf32(Wih0[n * I_DIM + k + 4]);
    }
}

// ---------------------------------------------------------------------------
// GEMM0: xg[M, 256] = X[M, 128] @ W_ih0^T + bias, 1xTF32 tensor cores.
// Block tile 64(M) x 128(N); 8 warps = 4(M) x 2(N). grid = (M/64, 2).
// ---------------------------------------------------------------------------
__global__ void __launch_bounds__(256)
gemm_xg0_kernel(const float* __restrict__ X) {
    constexpr int K = I_DIM, KIT = K / 8, LDA = K + 4;
    __shared__ float Xs[64][LDA];

    int tid = threadIdx.x;
    int warp = tid >> 5, lane = tid & 31;
    int wm = warp >> 1, wn = warp & 1;
    int m0 = blockIdx.x * 64;

    const float4* Xg = (const float4*)(X + (size_t)m0 * K);
    for (int i = tid; i < 64 * K / 4; i += 256) {
        float4 v = Xg[i];
        int r = i / (K / 4), c = (i % (K / 4)) * 4;
        *(float4*)&Xs[r][c] = v;
    }
    __syncthreads();

    float acc[8][4];
#pragma unroll
    for (int nt = 0; nt < 8; nt++)
#pragma unroll
        for (int q = 0; q < 4; q++) acc[nt][q] = 0.0f;

    int row0 = wm * 16 + (lane >> 2);
    int kc = lane & 3;
    int gbase = blockIdx.y * 16 + wn * 8;

#pragma unroll 4
    for (int kit = 0; kit < KIT; kit++) {
        int k0 = kit * 8 + kc;
        uint32_t ah[4];
        ah[0] = f2tf32(Xs[row0][k0]);
        ah[1] = f2tf32(Xs[row0 + 8][k0]);
        ah[2] = f2tf32(Xs[row0][k0 + 4]);
        ah[3] = f2tf32(Xs[row0 + 8][k0 + 4]);
#pragma unroll
        for (int nt = 0; nt < 8; nt++) {
            const uint32_t* fb =
                (const uint32_t*)(g_bfrag0 + ((gbase + nt) * KIT + kit) * 128);
            uint2 bh = *(const uint2*)(fb + lane * 2);
            mma_tf32(acc[nt], ah, bh.x, bh.y);
        }
    }

    int crow = m0 + wm * 16 + (lane >> 2);
#pragma unroll
    for (int nt = 0; nt < 8; nt++) {
        int n0 = (gbase + nt) * 8 + (lane & 3) * 2;
        float b0 = g_bias0[n0], b1 = g_bias0[n0 + 1];
        size_t base = (size_t)crow * G_DIM + n0;
        *(float2*)&g_xg[base]             = make_float2(acc[nt][0] + b0, acc[nt][1] + b1);
        *(float2*)&g_xg[base + 8 * G_DIM] = make_float2(acc[nt][2] + b0, acc[nt][3] + b1);
    }
}

// ---------------------------------------------------------------------------
// LSTM layer 0: persistent, 128 blocks x 8 batch rows, 256 threads.
// Gate-per-tile mapping: n(t4) = t4*64 + warp*8 (+ frag row) -> after the 4
// MMAs each thread holds i,f,g,o for ITS two cells (arow, hc), (arow, hc+1)
// -> in-thread cell update, no gate exchange. Double-buffered h_s ->
// exactly ONE barrier per step. W_hh frags register-resident.
// ---------------------------------------------------------------------------
__global__ void __launch_bounds__(256, 1)
lstm0_kernel(const float* __restrict__ Whh) {
    __shared__ float h_s[2][8][68];    // (4r + c) % 32 distinct -> conflict-free

    int tid = threadIdx.x;
    int warp = tid >> 5, lane = tid & 31;
    int arow = lane >> 2, kc = lane & 3;
    int r0 = blockIdx.x * 8;
    int hc = warp * 8 + 2 * kc;        // this thread's 2 h-columns: hc, hc+1

    // W_hh frags: n = t4*64 + warp*8 + arow, k = kit*8 + kc  (verified layout)
    uint32_t wb[4][8][2];
#pragma unroll
    for (int t4 = 0; t4 < 4; t4++) {
        int n = t4 * 64 + warp * 8 + arow;
#pragma unroll
        for (int kit = 0; kit < 8; kit++) {
            int k = kit * 8 + kc;
            wb[t4][kit][0] = f2tf32(Whh[n * H_DIM + k]);
            wb[t4][kit][1] = f2tf32(Whh[n * H_DIM + k + 4]);
        }
    }
    for (int i = tid; i < 2 * 8 * 68; i += 256) ((float*)h_s)[i] = 0.0f;

    float c0 = 0.0f, c1 = 0.0f;

    const float* xgp[4];
    float2 xgv[4];
#pragma unroll
    for (int t4 = 0; t4 < 4; t4++) {
        xgp[t4] = g_xg + ((size_t)(r0 + arow) * T_STEPS) * G_DIM + t4 * 64 + hc;
        xgv[t4] = *(const float2*)xgp[t4];
    }
    __syncthreads();

    int p = 0;
    for (int t = 0; t < T_STEPS; t++) {
        float acc[4][4];
#pragma unroll
        for (int t4 = 0; t4 < 4; t4++) {
            acc[t4][0] = xgv[t4].x; acc[t4][1] = xgv[t4].y;
            acc[t4][2] = 0.0f;      acc[t4][3] = 0.0f;
        }
#pragma unroll
        for (int kit = 0; kit < 8; kit++) {
            int k0 = kit * 8 + kc;
            uint32_t a[4];
            a[0] = f2tf32(h_s[p][arow][k0]);
            a[2] = f2tf32(h_s[p][arow][k0 + 4]);
            a[1] = 0u; a[3] = 0u;              // padded M rows 8..15
#pragma unroll
            for (int t4 = 0; t4 < 4; t4++)
                mma_tf32(acc[t4], a, wb[t4][kit][0], wb[t4][kit][1]);
        }
        if (t + 1 < T_STEPS) {
#pragma unroll
            for (int t4 = 0; t4 < 4; t4++) {
                xgp[t4] += G_DIM;
                xgv[t4] = *(const float2*)xgp[t4];
            }
        }
        // in-thread gates: t4 = 0:i 1:f 2:g 3:o at (arow, hc/hc+1)
        float i0 = fast_sigmoid(acc[0][0]), i1 = fast_sigmoid(acc[0][1]);
        float f0 = fast_sigmoid(acc[1][0]), f1 = fast_sigmoid(acc[1][1]);
        float gg0 = fast_tanh(acc[2][0]),   gg1 = fast_tanh(acc[2][1]);
        float o0 = fast_sigmoid(acc[3][0]), o1 = fast_sigmoid(acc[3][1]);
        c0 = fmaf(f0, c0, i0 * gg0);
        c1 = fmaf(f1, c1, i1 * gg1);
        float h0 = o0 * fast_tanh(c0);
        float h1 = o1 * fast_tanh(c1);

        h_s[p ^ 1][arow][hc]     = h0;
        h_s[p ^ 1][arow][hc + 1] = h1;
        *(float2*)&g_out1[((size_t)(r0 + arow) * T_STEPS + t) * H_DIM + hc] =
            make_float2(h0, h1);
        __syncthreads();
        p ^= 1;
    }
}

// ---------------------------------------------------------------------------
// LSTM layer 1, FUSED input GEMM: gates = [x_t | h] @ [W_ih1; W_hh1]^T + b.
// Concat K = 128 -> 16 k-iters; all 128 weight frags register-resident.
// x_t (= out1[:, t, :]) prefetched one step ahead into double-buffered x_s.
// Same in-thread update, ONE barrier per step. Writes only h_T.
// ---------------------------------------------------------------------------
__global__ void __launch_bounds__(256, 1)
lstm1_fused_kernel(const float* __restrict__ Wih, const float* __restrict__ Whh) {
    __shared__ float h_s[2][8][68];
    __shared__ float x_s[2][8][68];

    int tid = threadIdx.x;
    int warp = tid >> 5, lane = tid & 31;
    int arow = lane >> 2, kc = lane & 3;
    int r0 = blockIdx.x * 8;
    int hc = warp * 8 + 2 * kc;

    // weight frags: kit 0..7 -> W_ih1 (x part), kit 8..15 -> W_hh1 (h part)
    uint32_t wb[4][16][2];
#pragma unroll
    for (int t4 = 0; t4 < 4; t4++) {
        int n = t4 * 64 + warp * 8 + arow;
#pragma unroll
        for (int kit = 0; kit < 16; kit++) {
            const float* W = (kit < 8) ? Wih : Whh;
            int k = (kit & 7) * 8 + kc;
            wb[t4][kit][0] = f2tf32(W[n * H_DIM + k]);
            wb[t4][kit][1] = f2tf32(W[n * H_DIM + k + 4]);
        }
    }
    float2 bv[4];
#pragma unroll
    for (int t4 = 0; t4 < 4; t4++)
        bv[t4] = *(const float2*)&g_bias1[t4 * 64 + hc];

    for (int i = tid; i < 2 * 8 * 68; i += 256) ((float*)h_s)[i] = 0.0f;

    // x_s[0] <- out1[:, t=0, :]   (thread: row tid>>5, cols lane*2..+1)
    int xr = tid >> 5;
    {
        float2 v = *(const float2*)&g_out1[((size_t)(r0 + xr) * T_STEPS) * H_DIM + lane * 2];
        *(float2*)&x_s[0][xr][lane * 2] = v;
    }
    float c0 = 0.0f, c1 = 0.0f;
    __syncthreads();

    int p = 0;
    for (int t = 0; t < T_STEPS; t++) {
        float acc[4][4];
#pragma unroll
        for (int t4 = 0; t4 < 4; t4++) {
            acc[t4][0] = bv[t4].x; acc[t4][1] = bv[t4].y;
            acc[t4][2] = 0.0f;     acc[t4][3] = 0.0f;
        }
#pragma unroll
        for (int kit = 0; kit < 16; kit++) {
            int k0 = (kit & 7) * 8 + kc;
            const float* src = (kit < 8) ? &x_s[p][arow][0] : &h_s[p][arow][0];
            uint32_t a[4];
            a[0] = f2tf32(src[k0]);
            a[2] = f2tf32(src[k0 + 4]);
            a[1] = 0u; a[3] = 0u;
#pragma unroll
            for (int t4 = 0; t4 < 4; t4++)
                mma_tf32(acc[t4], a, wb[t4][kit][0], wb[t4][kit][1]);
        }
        // prefetch next x_t
        float2 xv = make_float2(0.0f, 0.0f);
        if (t + 1 < T_STEPS)
            xv = *(const float2*)&g_out1[((size_t)(r0 + xr) * T_STEPS + t + 1) * H_DIM + lane * 2];

        float i0 = fast_sigmoid(acc[0][0]), i1 = fast_sigmoid(acc[0][1]);
        float f0 = fast_sigmoid(acc[1][0]), f1 = fast_sigmoid(acc[1][1]);
        float gg0 = fast_tanh(acc[2][0]),   gg1 = fast_tanh(acc[2][1]);
        float o0 = fast_sigmoid(acc[3][0]), o1 = fast_sigmoid(acc[3][1]);
        c0 = fmaf(f0, c0, i0 * gg0);
        c1 = fmaf(f1, c1, i1 * gg1);
        float h0 = o0 * fast_tanh(c0);
        float h1 = o1 * fast_tanh(c1);

        h_s[p ^ 1][arow][hc]     = h0;
        h_s[p ^ 1][arow][hc + 1] = h1;
        *(float2*)&x_s[p ^ 1][xr][lane * 2] = xv;
        if (t == T_STEPS - 1)
            *(float2*)&g_hlast[(r0 + arow) * H_DIM + hc] = make_float2(h0, h1);
        __syncthreads();
        p ^= 1;
    }
}

// ---------------------------------------------------------------------------
// Head: logits = relu(relu(h_last@Wproj^T+b)@Wfc1^T+b)@Wfc2^T+b
// ---------------------------------------------------------------------------
__global__ void __launch_bounds__(128)
head_kernel(const float* __restrict__ Wproj, const float* __restrict__ bproj,
            const float* __restrict__ Wfc1,  const float* __restrict__ bfc1,
            const float* __restrict__ Wfc2,  const float* __restrict__ bfc2,
            float* __restrict__ out) {
    __shared__ float hs[64], emb[128], hid[128];
    int t = threadIdx.x;
    int row = blockIdx.x;
    if (t < 64) hs[t] = g_hlast[row * H_DIM + t];
    __syncthreads();
    {
        const float* w = Wproj + t * H_DIM;
        float s0 = 0, s1 = 0, s2 = 0, s3 = 0;
#pragma unroll
        for (int k = 0; k < H_DIM; k += 4) {
            s0 = fmaf(w[k],     hs[k],     s0);
            s1 = fmaf(w[k + 1], hs[k + 1], s1);
            s2 = fmaf(w[k + 2], hs[k + 2], s2);
            s3 = fmaf(w[k + 3], hs[k + 3], s3);
        }
        emb[t] = fmaxf((s0 + s1) + (s2 + s3) + bproj[t], 0.0f);
    }
    __syncthreads();
    {
        const float* w = Wfc1 + t * E_DIM;
        float s0 = 0, s1 = 0, s2 = 0, s3 = 0;
#pragma unroll
        for (int k = 0; k < E_DIM; k += 4) {
            s0 = fmaf(w[k],     emb[k],     s0);
            s1 = fmaf(w[k + 1], emb[k + 1], s1);
            s2 = fmaf(w[k + 2], emb[k + 2], s2);
            s3 = fmaf(w[k + 3], emb[k + 3], s3);
        }
        hid[t] = fmaxf((s0 + s1) + (s2 + s3) + bfc1[t], 0.0f);
    }
    __syncthreads();
    if (t < C_DIM) {
        const float* w = Wfc2 + t * E_DIM;
        float s0 = 0, s1 = 0, s2 = 0, s3 = 0;
#pragma unroll
        for (int k = 0; k < E_DIM; k += 4) {
            s0 = fmaf(w[k],     hid[k],     s0);
            s1 = fmaf(w[k + 1], hid[k + 1], s1);
            s2 = fmaf(w[k + 2], hid[k + 2], s2);
            s3 = fmaf(w[k + 3], hid[k + 3], s3);
        }
        out[row * C_DIM + t] = (s0 + s1) + (s2 + s3) + bfc2[t];
    }
}

// ---------------------------------------------------------------------------
// Launch: prep -> gemm0 -> lstm0 -> lstm1(fused) -> head
// ---------------------------------------------------------------------------
extern "C" void kernel_launch(void* const* d_in, const int* in_sizes, int n_in,
                              void* d_out, int out_size) {
    const float* x     = (const float*)d_in[0];
    const float* Wih0  = (const float*)d_in[1];
    const float* Whh0  = (const float*)d_in[2];
    const float* bih0  = (const float*)d_in[3];
    const float* bhh0  = (const float*)d_in[4];
    const float* Wih1  = (const float*)d_in[5];
    const float* Whh1  = (const float*)d_in[6];
    const float* bih1  = (const float*)d_in[7];
    const float* bhh1  = (const float*)d_in[8];
    const float* Wproj = (const float*)d_in[9];
    const float* bproj = (const float*)d_in[10];
    const float* Wfc1  = (const float*)d_in[11];
    const float* bfc1  = (const float*)d_in[12];
    const float* Wfc2  = (const float*)d_in[13];
    const float* bfc2  = (const float*)d_in[14];
    float* out = (float*)d_out;

    prep_kernel<<<64, 512>>>(Wih0, bih0, bhh0, bih1, bhh1);

    gemm_xg0_kernel<<<dim3(M_ROWS / 64, 2), 256>>>(x);
    lstm0_kernel<<<B_SZ / 8, 256>>>(Whh0);
    lstm1_fused_kernel<<<B_SZ / 8, 256>>>(Wih1, Whh1);

    head_kernel<<<B_SZ, 128>>>(Wproj, bproj, Wfc1, bfc1, Wfc2, bfc2, out);
}

// round 16
// speedup vs baseline: 1.3783x; 1.3783x over previous
#include <cuda_runtime.h>
#include <cuda_bf16.h>
#include <cstdint>

// ---------------------------------------------------------------------------
// Problem constants
//   x: [1024, 512, 128] fp32 -> logits [1024, 100] fp32
// ---------------------------------------------------------------------------
#define B_SZ    1024
#define T_STEPS 512
#define I_DIM   128
#define H_DIM   64
#define G_DIM   256                   // 4*H gate columns
#define E_DIM   128
#define C_DIM   100
#define M_ROWS  (B_SZ * T_STEPS)      // 524288

// ---------------------------------------------------------------------------
// Scratch (allocations forbidden -> __device__ globals)
// ---------------------------------------------------------------------------
__device__ uint32_t g_out1u[(size_t)M_ROWS * 32]; // layer-0 h sequence, bf16x2 (67 MB)
__device__ float    g_hlast[B_SZ * H_DIM];        // layer-1 final hidden (fp32)

// ---------------------------------------------------------------------------
// PTX helpers
// ---------------------------------------------------------------------------
// pack {lo, hi} floats -> bf16x2 register (cvt.rn.bf16x2.f32 d, hi, lo)
__device__ __forceinline__ uint32_t packbf(float lo, float hi) {
    uint32_t r;
    asm("cvt.rn.bf16x2.f32 %0, %1, %2;" : "=r"(r) : "f"(hi), "f"(lo));
    return r;
}

// m16n8k16 row.col bf16 MMA, fp32 accumulate. C layout == m16n8k8 case:
// c0,c1 = (row lane/4, cols 2*(lane%4), +1); c2,c3 = row+8 (our zero rows).
__device__ __forceinline__ void mma_bf16(float* d, uint32_t a0, uint32_t a1,
                                         uint32_t a2, uint32_t a3,
                                         uint32_t b0, uint32_t b1) {
    asm volatile(
        "mma.sync.aligned.m16n8k16.row.col.f32.bf16.bf16.f32 "
        "{%0,%1,%2,%3}, {%4,%5,%6,%7}, {%8,%9}, {%0,%1,%2,%3};"
        : "+f"(d[0]), "+f"(d[1]), "+f"(d[2]), "+f"(d[3])
        : "r"(a0), "r"(a1), "r"(a2), "r"(a3), "r"(b0), "r"(b1));
}

__device__ __forceinline__ float frcp(float x) {      // MUFU.RCP
    float r;
    asm("rcp.approx.f32 %0, %1;" : "=f"(r) : "f"(x));
    return r;
}
__device__ __forceinline__ float fast_sigmoid(float x) {
    return frcp(1.0f + __expf(-x));                   // ex2 + rcp, inf-safe
}
__device__ __forceinline__ float fast_tanh(float x) {
    return 2.0f * frcp(1.0f + __expf(-2.0f * x)) - 1.0f;
}

// ---------------------------------------------------------------------------
// bf16 m16n8k16 fragment conventions used below (lane g = lane>>2, kc = lane&3):
//   A (16 x 16):  a0 = {A[g][2kc],   A[g][2kc+1]}   a2 = {A[g][2kc+8], A[g][2kc+9]}
//                 a1 = a3 = 0  (rows 8..15 padded with zeros)
//   B (16 x 8):   b0 = {W[n][2kc],  W[n][2kc+1]}    b1 = {W[n][2kc+8], W[n][2kc+9]}
//                 with n = t4*64 + warp*8 + g   (gate-per-tile mapping: t4 = i,f,g,o)
// h/x tiles live in SMEM as bf16x2 words; pair index for k-chunk `kit`:
//   a0 word = kit*8 + kc, a2 word = kit*8 + 4 + kc.
// SMEM row pads (36 / 68 words) keep (4*row + kc) bank-distinct for both
// the MMA reads and the STS patterns.
// ---------------------------------------------------------------------------

// ---------------------------------------------------------------------------
// LSTM layer 0, FULLY FUSED input GEMM:
//   gates = [x_t | h] @ [W_ih0 ; W_hh0]^T + (b_ih0 + b_hh0)
// Concat K = 128 + 64 = 192 -> 12 bf16 k-iters, all weight frags in registers.
// 128 persistent blocks x 8 batch rows; in-thread cell update (gate-per-tile),
// double-buffered h_s/x_s -> ONE barrier per step. x_t LDG issued at the top
// of each step (full step of latency slack), cvt+STS just before the barrier.
// Writes the full h sequence as bf16x2 into g_out1u.
// ---------------------------------------------------------------------------
__global__ void __launch_bounds__(256, 1)
lstm0_fused_kernel(const float* __restrict__ x,
                   const float* __restrict__ Wih, const float* __restrict__ Whh,
                   const float* __restrict__ bih, const float* __restrict__ bhh) {
    __shared__ uint32_t h_s[2][8][36];   // h as bf16x2, 32 words + pad
    __shared__ uint32_t x_s[2][8][68];   // x_t as bf16x2, 64 words + pad

    int tid = threadIdx.x;
    int warp = tid >> 5, lane = tid & 31;
    int arow = lane >> 2, kc = lane & 3;
    int r0 = blockIdx.x * 8;
    int hc = warp * 8 + 2 * kc;          // this thread's 2 h-columns

    // ---- weight fragments: kits 0..7 = W_ih0 (K=128), 8..11 = W_hh0 (K=64) ----
    uint32_t wb[4][12][2];
#pragma unroll
    for (int t4 = 0; t4 < 4; t4++) {
        int n = t4 * 64 + warp * 8 + arow;
#pragma unroll
        for (int kit = 0; kit < 12; kit++) {
            const float* W = (kit < 8) ? (Wih + n * I_DIM + kit * 16)
                                       : (Whh + n * H_DIM + (kit - 8) * 16);
            int k = kc * 2;
            wb[t4][kit][0] = packbf(W[k],     W[k + 1]);
            wb[t4][kit][1] = packbf(W[k + 8], W[k + 9]);
        }
    }
    // folded bias pair for each gate tile
    float2 bv[4];
#pragma unroll
    for (int t4 = 0; t4 < 4; t4++) {
        int n0 = t4 * 64 + hc;
        bv[t4] = make_float2(bih[n0] + bhh[n0], bih[n0 + 1] + bhh[n0 + 1]);
    }

    for (int i = tid; i < 2 * 8 * 36; i += 256) ((uint32_t*)h_s)[i] = 0u;

    // stage x(t=0) into x_s[0]: thread row = warp, bf16x2 cols lane, lane+32
    {
        const float2* xr = (const float2*)(x + ((size_t)(r0 + warp) * T_STEPS) * I_DIM);
        float2 v0 = xr[lane], v1 = xr[lane + 32];
        x_s[0][warp][lane]      = packbf(v0.x, v0.y);
        x_s[0][warp][lane + 32] = packbf(v1.x, v1.y);
    }
    float c0 = 0.0f, c1 = 0.0f;
    __syncthreads();

    int p = 0;
    for (int t = 0; t < T_STEPS; t++) {
        // ---- prefetch x(t+1): issue LDG first, consume at step end ----
        float2 xa = make_float2(0.f, 0.f), xb = xa;
        if (t + 1 < T_STEPS) {
            const float2* xr =
                (const float2*)(x + ((size_t)(r0 + warp) * T_STEPS + t + 1) * I_DIM);
            xa = xr[lane];
            xb = xr[lane + 32];
        }
        // ---- pre-gates: bias + [x|h] @ W^T ----
        float acc[4][4];
#pragma unroll
        for (int t4 = 0; t4 < 4; t4++) {
            acc[t4][0] = bv[t4].x; acc[t4][1] = bv[t4].y;
            acc[t4][2] = 0.0f;     acc[t4][3] = 0.0f;
        }
#pragma unroll
        for (int kit = 0; kit < 12; kit++) {
            uint32_t a0, a2;
            if (kit < 8) {
                a0 = x_s[p][arow][kit * 8 + kc];
                a2 = x_s[p][arow][kit * 8 + 4 + kc];
            } else {
                a0 = h_s[p][arow][(kit - 8) * 8 + kc];
                a2 = h_s[p][arow][(kit - 8) * 8 + 4 + kc];
            }
#pragma unroll
            for (int t4 = 0; t4 < 4; t4++)
                mma_bf16(acc[t4], a0, 0u, a2, 0u, wb[t4][kit][0], wb[t4][kit][1]);
        }
        // ---- in-thread gates (t4 = i,f,g,o) and cell update ----
        float i0 = fast_sigmoid(acc[0][0]), i1 = fast_sigmoid(acc[0][1]);
        float f0 = fast_sigmoid(acc[1][0]), f1 = fast_sigmoid(acc[1][1]);
        float gg0 = fast_tanh(acc[2][0]),   gg1 = fast_tanh(acc[2][1]);
        float o0 = fast_sigmoid(acc[3][0]), o1 = fast_sigmoid(acc[3][1]);
        c0 = fmaf(f0, c0, i0 * gg0);
        c1 = fmaf(f1, c1, i1 * gg1);
        float h0 = o0 * fast_tanh(c0);
        float h1 = o1 * fast_tanh(c1);

        uint32_t hp = packbf(h0, h1);
        h_s[p ^ 1][arow][warp * 4 + kc] = hp;
        g_out1u[((size_t)(r0 + arow) * T_STEPS + t) * 32 + warp * 4 + kc] = hp;
        x_s[p ^ 1][warp][lane]      = packbf(xa.x, xa.y);
        x_s[p ^ 1][warp][lane + 32] = packbf(xb.x, xb.y);
        __syncthreads();
        p ^= 1;
    }
}

// ---------------------------------------------------------------------------
// LSTM layer 1, fused: gates = [x_t | h] @ [W_ih1 ; W_hh1]^T + b  (K = 128,
// 8 bf16 k-iters). x_t = out1[:, t, :] read as bf16x2 (one coalesced LDG /
// thread, full step of slack). Writes only h_T (fp32).
// ---------------------------------------------------------------------------
__global__ void __launch_bounds__(256, 1)
lstm1_fused_kernel(const float* __restrict__ Wih, const float* __restrict__ Whh,
                   const float* __restrict__ bih, const float* __restrict__ bhh) {
    __shared__ uint32_t h_s[2][8][36];
    __shared__ uint32_t x_s[2][8][36];

    int tid = threadIdx.x;
    int warp = tid >> 5, lane = tid & 31;
    int arow = lane >> 2, kc = lane & 3;
    int r0 = blockIdx.x * 8;
    int hc = warp * 8 + 2 * kc;

    // weight fragments: kits 0..3 = W_ih1, 4..7 = W_hh1 (both K=64)
    uint32_t wb[4][8][2];
#pragma unroll
    for (int t4 = 0; t4 < 4; t4++) {
        int n = t4 * 64 + warp * 8 + arow;
#pragma unroll
        for (int kit = 0; kit < 8; kit++) {
            const float* W = (kit < 4) ? (Wih + n * H_DIM + kit * 16)
                                       : (Whh + n * H_DIM + (kit - 4) * 16);
            int k = kc * 2;
            wb[t4][kit][0] = packbf(W[k],     W[k + 1]);
            wb[t4][kit][1] = packbf(W[k + 8], W[k + 9]);
        }
    }
    float2 bv[4];
#pragma unroll
    for (int t4 = 0; t4 < 4; t4++) {
        int n0 = t4 * 64 + hc;
        bv[t4] = make_float2(bih[n0] + bhh[n0], bih[n0 + 1] + bhh[n0 + 1]);
    }

    for (int i = tid; i < 2 * 8 * 36; i += 256) ((uint32_t*)h_s)[i] = 0u;

    // stage x(t=0): thread row = warp, word col = lane (coalesced 128B)
    x_s[0][warp][lane] =
        g_out1u[((size_t)(r0 + warp) * T_STEPS) * 32 + lane];
    float c0 = 0.0f, c1 = 0.0f;
    __syncthreads();

    int p = 0;
    for (int t = 0; t < T_STEPS; t++) {
        uint32_t xn = 0u;
        if (t + 1 < T_STEPS)
            xn = g_out1u[((size_t)(r0 + warp) * T_STEPS + t + 1) * 32 + lane];

        float acc[4][4];
#pragma unroll
        for (int t4 = 0; t4 < 4; t4++) {
            acc[t4][0] = bv[t4].x; acc[t4][1] = bv[t4].y;
            acc[t4][2] = 0.0f;     acc[t4][3] = 0.0f;
        }
#pragma unroll
        for (int kit = 0; kit < 8; kit++) {
            uint32_t a0, a2;
            if (kit < 4) {
                a0 = x_s[p][arow][kit * 8 + kc];
                a2 = x_s[p][arow][kit * 8 + 4 + kc];
            } else {
                a0 = h_s[p][arow][(kit - 4) * 8 + kc];
                a2 = h_s[p][arow][(kit - 4) * 8 + 4 + kc];
            }
#pragma unroll
            for (int t4 = 0; t4 < 4; t4++)
                mma_bf16(acc[t4], a0, 0u, a2, 0u, wb[t4][kit][0], wb[t4][kit][1]);
        }
        float i0 = fast_sigmoid(acc[0][0]), i1 = fast_sigmoid(acc[0][1]);
        float f0 = fast_sigmoid(acc[1][0]), f1 = fast_sigmoid(acc[1][1]);
        float gg0 = fast_tanh(acc[2][0]),   gg1 = fast_tanh(acc[2][1]);
        float o0 = fast_sigmoid(acc[3][0]), o1 = fast_sigmoid(acc[3][1]);
        c0 = fmaf(f0, c0, i0 * gg0);
        c1 = fmaf(f1, c1, i1 * gg1);
        float h0 = o0 * fast_tanh(c0);
        float h1 = o1 * fast_tanh(c1);

        h_s[p ^ 1][arow][warp * 4 + kc] = packbf(h0, h1);
        x_s[p ^ 1][warp][lane] = xn;
        if (t == T_STEPS - 1)
            *(float2*)&g_hlast[(r0 + arow) * H_DIM + hc] = make_float2(h0, h1);
        __syncthreads();
        p ^= 1;
    }
}

// ---------------------------------------------------------------------------
// Head: logits = relu(relu(h_last@Wproj^T+b)@Wfc1^T+b)@Wfc2^T+b
// One block per batch row; weights L1/L2-resident across blocks.
// ---------------------------------------------------------------------------
__global__ void __launch_bounds__(128)
head_kernel(const float* __restrict__ Wproj, const float* __restrict__ bproj,
            const float* __restrict__ Wfc1,  const float* __restrict__ bfc1,
            const float* __restrict__ Wfc2,  const float* __restrict__ bfc2,
            float* __restrict__ out) {
    __shared__ float hs[64], emb[128], hid[128];
    int t = threadIdx.x;
    int row = blockIdx.x;
    if (t < 64) hs[t] = g_hlast[row * H_DIM + t];
    __syncthreads();
    {
        const float* w = Wproj + t * H_DIM;
        float s0 = 0, s1 = 0, s2 = 0, s3 = 0;
#pragma unroll
        for (int k = 0; k < H_DIM; k += 4) {
            s0 = fmaf(w[k],     hs[k],     s0);
            s1 = fmaf(w[k + 1], hs[k + 1], s1);
            s2 = fmaf(w[k + 2], hs[k + 2], s2);
            s3 = fmaf(w[k + 3], hs[k + 3], s3);
        }
        emb[t] = fmaxf((s0 + s1) + (s2 + s3) + bproj[t], 0.0f);
    }
    __syncthreads();
    {
        const float* w = Wfc1 + t * E_DIM;
        float s0 = 0, s1 = 0, s2 = 0, s3 = 0;
#pragma unroll
        for (int k = 0; k < E_DIM; k += 4) {
            s0 = fmaf(w[k],     emb[k],     s0);
            s1 = fmaf(w[k + 1], emb[k + 1], s1);
            s2 = fmaf(w[k + 2], emb[k + 2], s2);
            s3 = fmaf(w[k + 3], emb[k + 3], s3);
        }
        hid[t] = fmaxf((s0 + s1) + (s2 + s3) + bfc1[t], 0.0f);
    }
    __syncthreads();
    if (t < C_DIM) {
        const float* w = Wfc2 + t * E_DIM;
        float s0 = 0, s1 = 0, s2 = 0, s3 = 0;
#pragma unroll
        for (int k = 0; k < E_DIM; k += 4) {
            s0 = fmaf(w[k],     hid[k],     s0);
            s1 = fmaf(w[k + 1], hid[k + 1], s1);
            s2 = fmaf(w[k + 2], hid[k + 2], s2);
            s3 = fmaf(w[k + 3], hid[k + 3], s3);
        }
        out[row * C_DIM + t] = (s0 + s1) + (s2 + s3) + bfc2[t];
    }
}

// ---------------------------------------------------------------------------
// Launch: lstm0(fully fused) -> lstm1(fused) -> head.  Three kernels total.
// ---------------------------------------------------------------------------
extern "C" void kernel_launch(void* const* d_in, const int* in_sizes, int n_in,
                              void* d_out, int out_size) {
    const float* x     = (const float*)d_in[0];
    const float* Wih0  = (const float*)d_in[1];
    const float* Whh0  = (const float*)d_in[2];
    const float* bih0  = (const float*)d_in[3];
    const float* bhh0  = (const float*)d_in[4];
    const float* Wih1  = (const float*)d_in[5];
    const float* Whh1  = (const float*)d_in[6];
    const float* bih1  = (const float*)d_in[7];
    const float* bhh1  = (const float*)d_in[8];
    const float* Wproj = (const float*)d_in[9];
    const float* bproj = (const float*)d_in[10];
    const float* Wfc1  = (const float*)d_in[11];
    const float* bfc1  = (const float*)d_in[12];
    const float* Wfc2  = (const float*)d_in[13];
    const float* bfc2  = (const float*)d_in[14];
    float* out = (float*)d_out;

    lstm0_fused_kernel<<<B_SZ / 8, 256>>>(x, Wih0, Whh0, bih0, bhh0);
    lstm1_fused_kernel<<<B_SZ / 8, 256>>>(Wih1, Whh1, bih1, bhh1);
    head_kernel<<<B_SZ, 128>>>(Wproj, bproj, Wfc1, bfc1, Wfc2, bfc2, out);
}

// round 17
// speedup vs baseline: 1.3801x; 1.0013x over previous
#include <cuda_runtime.h>
#include <cuda_bf16.h>
#include <cstdint>

// ---------------------------------------------------------------------------
// Problem constants
//   x: [1024, 512, 128] fp32 -> logits [1024, 100] fp32
// ---------------------------------------------------------------------------
#define B_SZ    1024
#define T_STEPS 512
#define I_DIM   128
#define H_DIM   64
#define G_DIM   256                   // 4*H gate columns
#define E_DIM   128
#define C_DIM   100
#define M_ROWS  (B_SZ * T_STEPS)      // 524288

// ---------------------------------------------------------------------------
// Scratch (allocations forbidden -> __device__ globals)
// ---------------------------------------------------------------------------
__device__ uint32_t g_out1u[(size_t)M_ROWS * 32]; // layer-0 h sequence, bf16x2 (67 MB)
__device__ float    g_hlast[B_SZ * H_DIM];        // layer-1 final hidden (fp32)

// ---------------------------------------------------------------------------
// PTX helpers
// ---------------------------------------------------------------------------
// pack {lo, hi} floats -> bf16x2 register (cvt.rn.bf16x2.f32 d, hi, lo)
__device__ __forceinline__ uint32_t packbf(float lo, float hi) {
    uint32_t r;
    asm("cvt.rn.bf16x2.f32 %0, %1, %2;" : "=r"(r) : "f"(hi), "f"(lo));
    return r;
}

// m16n8k16 row.col bf16 MMA, fp32 accumulate. C layout == m16n8k8 case:
// c0,c1 = (row lane/4, cols 2*(lane%4), +1); c2,c3 = row+8 (our zero rows).
__device__ __forceinline__ void mma_bf16(float* d, uint32_t a0, uint32_t a1,
                                         uint32_t a2, uint32_t a3,
                                         uint32_t b0, uint32_t b1) {
    asm volatile(
        "mma.sync.aligned.m16n8k16.row.col.f32.bf16.bf16.f32 "
        "{%0,%1,%2,%3}, {%4,%5,%6,%7}, {%8,%9}, {%0,%1,%2,%3};"
        : "+f"(d[0]), "+f"(d[1]), "+f"(d[2]), "+f"(d[3])
        : "r"(a0), "r"(a1), "r"(a2), "r"(a3), "r"(b0), "r"(b1));
}

__device__ __forceinline__ float frcp(float x) {      // MUFU.RCP
    float r;
    asm("rcp.approx.f32 %0, %1;" : "=f"(r) : "f"(x));
    return r;
}
__device__ __forceinline__ float fast_sigmoid(float x) {
    return frcp(1.0f + __expf(-x));                   // ex2 + rcp, inf-safe
}
__device__ __forceinline__ float fast_tanh(float x) {
    return 2.0f * frcp(1.0f + __expf(-2.0f * x)) - 1.0f;
}

// ---------------------------------------------------------------------------
// bf16 m16n8k16 fragment conventions used below (lane g = lane>>2, kc = lane&3):
//   A (16 x 16):  a0 = {A[g][2kc],   A[g][2kc+1]}   a2 = {A[g][2kc+8], A[g][2kc+9]}
//                 a1 = a3 = 0  (rows 8..15 padded with zeros)
//   B (16 x 8):   b0 = {W[n][2kc],  W[n][2kc+1]}    b1 = {W[n][2kc+8], W[n][2kc+9]}
//                 with n = t4*64 + warp*8 + g   (gate-per-tile mapping: t4 = i,f,g,o)
// h/x tiles live in SMEM as bf16x2 words; pair index for k-chunk `kit`:
//   a0 word = kit*8 + kc, a2 word = kit*8 + 4 + kc.
// SMEM row pads (36 / 68 words) keep (4*row + kc) bank-distinct for both
// the MMA reads and the STS patterns.
// ---------------------------------------------------------------------------

// ---------------------------------------------------------------------------
// LSTM layer 0, FULLY FUSED input GEMM:
//   gates = [x_t | h] @ [W_ih0 ; W_hh0]^T + (b_ih0 + b_hh0)
// Concat K = 128 + 64 = 192 -> 12 bf16 k-iters, all weight frags in registers.
// 128 persistent blocks x 8 batch rows; in-thread cell update (gate-per-tile),
// double-buffered h_s/x_s -> ONE barrier per step. x_t LDG issued at the top
// of each step (full step of latency slack), cvt+STS just before the barrier.
// Writes the full h sequence as bf16x2 into g_out1u.
// ---------------------------------------------------------------------------
__global__ void __launch_bounds__(256, 1)
lstm0_fused_kernel(const float* __restrict__ x,
                   const float* __restrict__ Wih, const float* __restrict__ Whh,
                   const float* __restrict__ bih, const float* __restrict__ bhh) {
    __shared__ uint32_t h_s[2][8][36];   // h as bf16x2, 32 words + pad
    __shared__ uint32_t x_s[2][8][68];   // x_t as bf16x2, 64 words + pad

    int tid = threadIdx.x;
    int warp = tid >> 5, lane = tid & 31;
    int arow = lane >> 2, kc = lane & 3;
    int r0 = blockIdx.x * 8;
    int hc = warp * 8 + 2 * kc;          // this thread's 2 h-columns

    // ---- weight fragments: kits 0..7 = W_ih0 (K=128), 8..11 = W_hh0 (K=64) ----
    uint32_t wb[4][12][2];
#pragma unroll
    for (int t4 = 0; t4 < 4; t4++) {
        int n = t4 * 64 + warp * 8 + arow;
#pragma unroll
        for (int kit = 0; kit < 12; kit++) {
            const float* W = (kit < 8) ? (Wih + n * I_DIM + kit * 16)
                                       : (Whh + n * H_DIM + (kit - 8) * 16);
            int k = kc * 2;
            wb[t4][kit][0] = packbf(W[k],     W[k + 1]);
            wb[t4][kit][1] = packbf(W[k + 8], W[k + 9]);
        }
    }
    // folded bias pair for each gate tile
    float2 bv[4];
#pragma unroll
    for (int t4 = 0; t4 < 4; t4++) {
        int n0 = t4 * 64 + hc;
        bv[t4] = make_float2(bih[n0] + bhh[n0], bih[n0 + 1] + bhh[n0 + 1]);
    }

    for (int i = tid; i < 2 * 8 * 36; i += 256) ((uint32_t*)h_s)[i] = 0u;

    // stage x(t=0) into x_s[0]: thread row = warp, bf16x2 cols lane, lane+32
    {
        const float2* xr = (const float2*)(x + ((size_t)(r0 + warp) * T_STEPS) * I_DIM);
        float2 v0 = xr[lane], v1 = xr[lane + 32];
        x_s[0][warp][lane]      = packbf(v0.x, v0.y);
        x_s[0][warp][lane + 32] = packbf(v1.x, v1.y);
    }
    float c0 = 0.0f, c1 = 0.0f;
    __syncthreads();

    int p = 0;
    for (int t = 0; t < T_STEPS; t++) {
        // ---- prefetch x(t+1): issue LDG first, consume at step end ----
        float2 xa = make_float2(0.f, 0.f), xb = xa;
        if (t + 1 < T_STEPS) {
            const float2* xr =
                (const float2*)(x + ((size_t)(r0 + warp) * T_STEPS + t + 1) * I_DIM);
            xa = xr[lane];
            xb = xr[lane + 32];
        }
        // ---- pre-gates: bias + [x|h] @ W^T ----
        float acc[4][4];
#pragma unroll
        for (int t4 = 0; t4 < 4; t4++) {
            acc[t4][0] = bv[t4].x; acc[t4][1] = bv[t4].y;
            acc[t4][2] = 0.0f;     acc[t4][3] = 0.0f;
        }
#pragma unroll
        for (int kit = 0; kit < 12; kit++) {
            uint32_t a0, a2;
            if (kit < 8) {
                a0 = x_s[p][arow][kit * 8 + kc];
                a2 = x_s[p][arow][kit * 8 + 4 + kc];
            } else {
                a0 = h_s[p][arow][(kit - 8) * 8 + kc];
                a2 = h_s[p][arow][(kit - 8) * 8 + 4 + kc];
            }
#pragma unroll
            for (int t4 = 0; t4 < 4; t4++)
                mma_bf16(acc[t4], a0, 0u, a2, 0u, wb[t4][kit][0], wb[t4][kit][1]);
        }
        // ---- in-thread gates (t4 = i,f,g,o) and cell update ----
        float i0 = fast_sigmoid(acc[0][0]), i1 = fast_sigmoid(acc[0][1]);
        float f0 = fast_sigmoid(acc[1][0]), f1 = fast_sigmoid(acc[1][1]);
        float gg0 = fast_tanh(acc[2][0]),   gg1 = fast_tanh(acc[2][1]);
        float o0 = fast_sigmoid(acc[3][0]), o1 = fast_sigmoid(acc[3][1]);
        c0 = fmaf(f0, c0, i0 * gg0);
        c1 = fmaf(f1, c1, i1 * gg1);
        float h0 = o0 * fast_tanh(c0);
        float h1 = o1 * fast_tanh(c1);

        uint32_t hp = packbf(h0, h1);
        h_s[p ^ 1][arow][warp * 4 + kc] = hp;
        g_out1u[((size_t)(r0 + arow) * T_STEPS + t) * 32 + warp * 4 + kc] = hp;
        x_s[p ^ 1][warp][lane]      = packbf(xa.x, xa.y);
        x_s[p ^ 1][warp][lane + 32] = packbf(xb.x, xb.y);
        __syncthreads();
        p ^= 1;
    }
}

// ---------------------------------------------------------------------------
// LSTM layer 1, fused: gates = [x_t | h] @ [W_ih1 ; W_hh1]^T + b  (K = 128,
// 8 bf16 k-iters). x_t = out1[:, t, :] read as bf16x2 (one coalesced LDG /
// thread, full step of slack). Writes only h_T (fp32).
// ---------------------------------------------------------------------------
__global__ void __launch_bounds__(256, 1)
lstm1_fused_kernel(const float* __restrict__ Wih, const float* __restrict__ Whh,
                   const float* __restrict__ bih, const float* __restrict__ bhh) {
    __shared__ uint32_t h_s[2][8][36];
    __shared__ uint32_t x_s[2][8][36];

    int tid = threadIdx.x;
    int warp = tid >> 5, lane = tid & 31;
    int arow = lane >> 2, kc = lane & 3;
    int r0 = blockIdx.x * 8;
    int hc = warp * 8 + 2 * kc;

    // weight fragments: kits 0..3 = W_ih1, 4..7 = W_hh1 (both K=64)
    uint32_t wb[4][8][2];
#pragma unroll
    for (int t4 = 0; t4 < 4; t4++) {
        int n = t4 * 64 + warp * 8 + arow;
#pragma unroll
        for (int kit = 0; kit < 8; kit++) {
            const float* W = (kit < 4) ? (Wih + n * H_DIM + kit * 16)
                                       : (Whh + n * H_DIM + (kit - 4) * 16);
            int k = kc * 2;
            wb[t4][kit][0] = packbf(W[k],     W[k + 1]);
            wb[t4][kit][1] = packbf(W[k + 8], W[k + 9]);
        }
    }
    float2 bv[4];
#pragma unroll
    for (int t4 = 0; t4 < 4; t4++) {
        int n0 = t4 * 64 + hc;
        bv[t4] = make_float2(bih[n0] + bhh[n0], bih[n0 + 1] + bhh[n0 + 1]);
    }

    for (int i = tid; i < 2 * 8 * 36; i += 256) ((uint32_t*)h_s)[i] = 0u;

    // stage x(t=0): thread row = warp, word col = lane (coalesced 128B)
    x_s[0][warp][lane] =
        g_out1u[((size_t)(r0 + warp) * T_STEPS) * 32 + lane];
    float c0 = 0.0f, c1 = 0.0f;
    __syncthreads();

    int p = 0;
    for (int t = 0; t < T_STEPS; t++) {
        uint32_t xn = 0u;
        if (t + 1 < T_STEPS)
            xn = g_out1u[((size_t)(r0 + warp) * T_STEPS + t + 1) * 32 + lane];

        float acc[4][4];
#pragma unroll
        for (int t4 = 0; t4 < 4; t4++) {
            acc[t4][0] = bv[t4].x; acc[t4][1] = bv[t4].y;
            acc[t4][2] = 0.0f;     acc[t4][3] = 0.0f;
        }
#pragma unroll
        for (int kit = 0; kit < 8; kit++) {
            uint32_t a0, a2;
            if (kit < 4) {
                a0 = x_s[p][arow][kit * 8 + kc];
                a2 = x_s[p][arow][kit * 8 + 4 + kc];
            } else {
                a0 = h_s[p][arow][(kit - 4) * 8 + kc];
                a2 = h_s[p][arow][(kit - 4) * 8 + 4 + kc];
            }
#pragma unroll
            for (int t4 = 0; t4 < 4; t4++)
                mma_bf16(acc[t4], a0, 0u, a2, 0u, wb[t4][kit][0], wb[t4][kit][1]);
        }
        float i0 = fast_sigmoid(acc[0][0]), i1 = fast_sigmoid(acc[0][1]);
        float f0 = fast_sigmoid(acc[1][0]), f1 = fast_sigmoid(acc[1][1]);
        float gg0 = fast_tanh(acc[2][0]),   gg1 = fast_tanh(acc[2][1]);
        float o0 = fast_sigmoid(acc[3][0]), o1 = fast_sigmoid(acc[3][1]);
        c0 = fmaf(f0, c0, i0 * gg0);
        c1 = fmaf(f1, c1, i1 * gg1);
        float h0 = o0 * fast_tanh(c0);
        float h1 = o1 * fast_tanh(c1);

        h_s[p ^ 1][arow][warp * 4 + kc] = packbf(h0, h1);
        x_s[p ^ 1][warp][lane] = xn;
        if (t == T_STEPS - 1)
            *(float2*)&g_hlast[(r0 + arow) * H_DIM + hc] = make_float2(h0, h1);
        __syncthreads();
        p ^= 1;
    }
}

// ---------------------------------------------------------------------------
// Head: logits = relu(relu(h_last@Wproj^T+b)@Wfc1^T+b)@Wfc2^T+b
// One block per batch row; weights L1/L2-resident across blocks.
// ---------------------------------------------------------------------------
__global__ void __launch_bounds__(128)
head_kernel(const float* __restrict__ Wproj, const float* __restrict__ bproj,
            const float* __restrict__ Wfc1,  const float* __restrict__ bfc1,
            const float* __restrict__ Wfc2,  const float* __restrict__ bfc2,
            float* __restrict__ out) {
    __shared__ float hs[64], emb[128], hid[128];
    int t = threadIdx.x;
    int row = blockIdx.x;
    if (t < 64) hs[t] = g_hlast[row * H_DIM + t];
    __syncthreads();
    {
        const float* w = Wproj + t * H_DIM;
        float s0 = 0, s1 = 0, s2 = 0, s3 = 0;
#pragma unroll
        for (int k = 0; k < H_DIM; k += 4) {
            s0 = fmaf(w[k],     hs[k],     s0);
            s1 = fmaf(w[k + 1], hs[k + 1], s1);
            s2 = fmaf(w[k + 2], hs[k + 2], s2);
            s3 = fmaf(w[k + 3], hs[k + 3], s3);
        }
        emb[t] = fmaxf((s0 + s1) + (s2 + s3) + bproj[t], 0.0f);
    }
    __syncthreads();
    {
        const float* w = Wfc1 + t * E_DIM;
        float s0 = 0, s1 = 0, s2 = 0, s3 = 0;
#pragma unroll
        for (int k = 0; k < E_DIM; k += 4) {
            s0 = fmaf(w[k],     emb[k],     s0);
            s1 = fmaf(w[k + 1], emb[k + 1], s1);
            s2 = fmaf(w[k + 2], emb[k + 2], s2);
            s3 = fmaf(w[k + 3], emb[k + 3], s3);
        }
        hid[t] = fmaxf((s0 + s1) + (s2 + s3) + bfc1[t], 0.0f);
    }
    __syncthreads();
    if (t < C_DIM) {
        const float* w = Wfc2 + t * E_DIM;
        float s0 = 0, s1 = 0, s2 = 0, s3 = 0;
#pragma unroll
        for (int k = 0; k < E_DIM; k += 4) {
            s0 = fmaf(w[k],     hid[k],     s0);
            s1 = fmaf(w[k + 1], hid[k + 1], s1);
            s2 = fmaf(w[k + 2], hid[k + 2], s2);
            s3 = fmaf(w[k + 3], hid[k + 3], s3);
        }
        out[row * C_DIM + t] = (s0 + s1) + (s2 + s3) + bfc2[t];
    }
}

// ---------------------------------------------------------------------------
// Launch: lstm0(fully fused) -> lstm1(fused) -> head.  Three kernels total.
// ---------------------------------------------------------------------------
extern "C" void kernel_launch(void* const* d_in, const int* in_sizes, int n_in,
                              void* d_out, int out_size) {
    const float* x     = (const float*)d_in[0];
    const float* Wih0  = (const float*)d_in[1];
    const float* Whh0  = (const float*)d_in[2];
    const float* bih0  = (const float*)d_in[3];
    const float* bhh0  = (const float*)d_in[4];
    const float* Wih1  = (const float*)d_in[5];
    const float* Whh1  = (const float*)d_in[6];
    const float* bih1  = (const float*)d_in[7];
    const float* bhh1  = (const float*)d_in[8];
    const float* Wproj = (const float*)d_in[9];
    const float* bproj = (const float*)d_in[10];
    const float* Wfc1  = (const float*)d_in[11];
    const float* bfc1  = (const float*)d_in[12];
    const float* Wfc2  = (const float*)d_in[13];
    const float* bfc2  = (const float*)d_in[14];
    float* out = (float*)d_out;

    lstm0_fused_kernel<<<B_SZ / 8, 256>>>(x, Wih0, Whh0, bih0, bhh0);
    lstm1_fused_kernel<<<B_SZ / 8, 256>>>(Wih1, Whh1, bih1, bhh1);
    head_kernel<<<B_SZ, 128>>>(Wproj, bproj, Wfc1, bfc1, Wfc2, bfc2, out);
}